// round 16
// baseline (speedup 1.0000x reference)
#include <cuda_runtime.h>
#include <cuda_fp16.h>
#include <cstdint>

// ---------------- problem constants ----------------
constexpr int HDIM = 2048;
constexpr int IDIM = 1408;
constexpr int NEXP = 16;
constexpr int TMAX = 8192;
constexpr int RMAX = 2 * TMAX;
constexpr int CAP  = RMAX;                    // per-expert row capacity
constexpr int TILE_MAX = RMAX / 128 + NEXP;   // 144 (all experts)
constexpr int HALF_MAX = RMAX / 128 + 8;      // 136 (one expert half, worst case)

// ---------------- device scratch (static, no runtime allocs) ----------------
__device__ int   g_counts[NEXP];
__device__ int   g_topk_i[RMAX];
__device__ float g_topk_w[RMAX];
__device__ int   g_rows_t[(size_t)NEXP * CAP];
__device__ float g_rows_w[(size_t)NEXP * CAP];
__device__ int   g_tile_e[TILE_MAX];
__device__ int   g_tile_m[TILE_MAX];
__device__ int   g_ntiles;
__device__ int   g_nt_half;   // tiles belonging to experts 0..7

__device__ alignas(16) __half g_w1h[(size_t)NEXP * HDIM * IDIM];  // [e][K=H][N=I]
__device__ alignas(16) __half g_w3h[(size_t)NEXP * HDIM * IDIM];
__device__ alignas(16) __half g_w2h[(size_t)NEXP * IDIM * HDIM];  // [e][K=I][N=H]
__device__ alignas(16) __half g_xh[(size_t)TMAX * HDIM];
__device__ alignas(16) __half g_hh[(size_t)NEXP * CAP * IDIM];

// ---------------- asm helpers ----------------
#define LDSM4(R, addr)                                                        \
  asm volatile("ldmatrix.sync.aligned.m8n8.x4.shared.b16 {%0,%1,%2,%3},[%4];" \
               : "=r"((R)[0]), "=r"((R)[1]), "=r"((R)[2]), "=r"((R)[3])       \
               : "r"(addr))

#define LDSM4T(R, addr)                                                             \
  asm volatile("ldmatrix.sync.aligned.m8n8.x4.trans.shared.b16 {%0,%1,%2,%3},[%4];" \
               : "=r"((R)[0]), "=r"((R)[1]), "=r"((R)[2]), "=r"((R)[3])             \
               : "r"(addr))

#define MMAF16(D, A, B)                                                       \
  asm volatile("mma.sync.aligned.m16n8k16.row.col.f32.f16.f16.f32 "           \
               "{%0,%1,%2,%3},{%4,%5,%6,%7},{%8,%9},{%0,%1,%2,%3};"           \
               : "+f"((D)[0]), "+f"((D)[1]), "+f"((D)[2]), "+f"((D)[3])       \
               : "r"((A)[0]), "r"((A)[1]), "r"((A)[2]), "r"((A)[3]),          \
                 "r"((B)[0]), "r"((B)[1]))

#define CP16(dst, src)                                                        \
  asm volatile("cp.async.cg.shared.global [%0],[%1],16;" ::"r"(dst), "l"(src))
#define CPCOMMIT() asm volatile("cp.async.commit_group;")
#define CPWAIT2() asm volatile("cp.async.wait_group 2;")

// ---------------- conversion pre-passes (side stream) ----------------
constexpr int NW4 = NEXP * HDIM * IDIM / 4;  // 11,534,336
constexpr int NW4H = NW4 / 2;                // 8 experts worth of float4

// convert expert-half `half` of w1 and w3
__global__ void convw13_kernel(const float* __restrict__ w1,
                               const float* __restrict__ w3, int half) {
  int i = blockIdx.x * blockDim.x + threadIdx.x;
  const float* src;
  __half* dst;
  int li;
  if (i < NW4H) {
    src = w1; dst = g_w1h; li = half * NW4H + i;
  } else {
    li = i - NW4H;
    if (li >= NW4H) return;
    src = w3; dst = g_w3h; li = half * NW4H + li;
  }
  float4 f = __ldcs(((const float4*)src) + li);
  __half2 a = __floats2half2_rn(f.x, f.y);
  __half2 b = __floats2half2_rn(f.z, f.w);
  uint2 u;
  u.x = *(const uint32_t*)&a;
  u.y = *(const uint32_t*)&b;
  ((uint2*)dst)[li] = u;
}

__global__ void convw2_kernel(const float* __restrict__ w2) {
  int i = blockIdx.x * blockDim.x + threadIdx.x;
  if (i >= NW4) return;
  float4 f = __ldcs(((const float4*)w2) + i);
  __half2 a = __floats2half2_rn(f.x, f.y);
  __half2 b = __floats2half2_rn(f.z, f.w);
  uint2 u;
  u.x = *(const uint32_t*)&a;
  u.y = *(const uint32_t*)&b;
  ((uint2*)g_w2h)[i] = u;
}

__global__ void join_kernel() {}

// ---------------- router: 4 tokens per warp; also emits g_xh (fp16) --------
// 128-thread blocks for better SM fill at 96 regs/thread.
__global__ void router_kernel(const float* __restrict__ x,
                              const float* __restrict__ gw, int T) {
  const int gwarp = (blockIdx.x * blockDim.x + threadIdx.x) >> 5;
  const int lane = threadIdx.x & 31;
  const int t0 = gwarp * 4;
  if (t0 >= T) return;

  const float* xr0 = x + (size_t)t0 * HDIM;
  __half* xh0 = g_xh + (size_t)t0 * HDIM;
  float acc[4][NEXP];
#pragma unroll
  for (int i = 0; i < 4; i++)
#pragma unroll
    for (int j = 0; j < NEXP; j++) acc[i][j] = 0.f;

  for (int k = lane; k < HDIM; k += 32) {
    const float4* g4 = (const float4*)(gw + (size_t)k * NEXP);
    float4 g0 = g4[0], g1 = g4[1], g2 = g4[2], g3 = g4[3];
    float xv0 = xr0[k];
    float xv1 = xr0[HDIM + k];
    float xv2 = xr0[2 * HDIM + k];
    float xv3 = xr0[3 * HDIM + k];
    xh0[k] = __float2half_rn(xv0);
    xh0[HDIM + k] = __float2half_rn(xv1);
    xh0[2 * HDIM + k] = __float2half_rn(xv2);
    xh0[3 * HDIM + k] = __float2half_rn(xv3);
#define RSTEP(i, xv)                                                          \
    acc[i][0] += (xv)*g0.x;  acc[i][1] += (xv)*g0.y;                          \
    acc[i][2] += (xv)*g0.z;  acc[i][3] += (xv)*g0.w;                          \
    acc[i][4] += (xv)*g1.x;  acc[i][5] += (xv)*g1.y;                          \
    acc[i][6] += (xv)*g1.z;  acc[i][7] += (xv)*g1.w;                          \
    acc[i][8] += (xv)*g2.x;  acc[i][9] += (xv)*g2.y;                          \
    acc[i][10] += (xv)*g2.z; acc[i][11] += (xv)*g2.w;                         \
    acc[i][12] += (xv)*g3.x; acc[i][13] += (xv)*g3.y;                         \
    acc[i][14] += (xv)*g3.z; acc[i][15] += (xv)*g3.w;
    RSTEP(0, xv0) RSTEP(1, xv1) RSTEP(2, xv2) RSTEP(3, xv3)
#undef RSTEP
  }
#pragma unroll
  for (int i = 0; i < 4; i++)
#pragma unroll
    for (int j = 0; j < NEXP; j++) {
#pragma unroll
      for (int o = 16; o > 0; o >>= 1)
        acc[i][j] += __shfl_xor_sync(0xffffffffu, acc[i][j], o);
    }

  if (lane < 4) {
    float v[NEXP];
#pragma unroll
    for (int j = 0; j < NEXP; j++) {
      float t = acc[0][j];
      if (lane == 1) t = acc[1][j];
      if (lane == 2) t = acc[2][j];
      if (lane == 3) t = acc[3][j];
      v[j] = t;
    }
    float b = -3.4e38f, s = -3.4e38f;
    int bi = 0, si = 0;
#pragma unroll
    for (int j = 0; j < NEXP; j++) {
      float w = v[j];
      if (w > b) { s = b; si = bi; b = w; bi = j; }
      else if (w > s) { s = w; si = j; }
    }
    float w0 = 1.f / (1.f + expf(s - b));
    int t = t0 + lane;
    g_topk_i[t * 2 + 0] = bi;
    g_topk_i[t * 2 + 1] = si;
    g_topk_w[t * 2 + 0] = w0;
    g_topk_w[t * 2 + 1] = 1.f - w0;
  }
}

// ---------------- direct per-expert scatter + tile map ----------------------
__global__ void scatter_kernel(int R) {
  int i = blockIdx.x * blockDim.x + threadIdx.x;
  if (i >= R) return;
  int e = g_topk_i[i];
  int p = atomicAdd(&g_counts[e], 1);
  g_rows_t[(size_t)e * CAP + p] = i >> 1;
  g_rows_w[(size_t)e * CAP + p] = g_topk_w[i];
}

__global__ void tilemap_kernel() {
  int nt = 0;
  for (int e = 0; e < NEXP; e++) {
    if (e == 8) g_nt_half = nt;
    int c = g_counts[e];
    for (int m = 0; m < c; m += 128) {
      g_tile_e[nt] = e;
      g_tile_m[nt] = m;
      nt++;
    }
  }
  g_ntiles = nt;
}

// ============================================================
// GEMM1: h = w * silu(Xe@w1) * (Xe@w3)   (single-pass fp16, weight folded)
// half=0: tiles [0, g_nt_half); half=1: tiles [g_nt_half, g_ntiles)
// BM=128, BN=64/matrix, BK=32, 256 thr, warps 4Mx2N, warp tile 32x32/matrix
// smem/stage (halves): A 128*40=5120 | B1 32*72=2304 | B3 2304 = 9728
// 4 stages, 2 CTAs/SM
// ============================================================
constexpr uint32_t G1_SST = 9728u * 2;

__global__ __launch_bounds__(256, 2) void gemm1_kernel(
    const __half* __restrict__ w1, const __half* __restrict__ w3, int half) {
  extern __shared__ __half sm[];
  const int tile = (half ? g_nt_half : 0) + blockIdx.x;
  const int tile_end = half ? g_ntiles : g_nt_half;
  if (tile >= tile_end) return;
  const int e = g_tile_e[tile];
  const int m0 = g_tile_m[tile];
  const size_t base = (size_t)e * CAP;
  const int cnt = g_counts[e];
  const int n0 = blockIdx.y * 64;

  const int tid = threadIdx.x, lane = tid & 31, warp = tid >> 5;
  const int wm = warp >> 1, wn = warp & 1;

  const int ar = tid >> 1, ak = (tid & 1) * 16;
  const int arow = m0 + ar;
  const int tokA = g_rows_t[base + (arow < cnt ? arow : cnt - 1)];
  const __half* pxh = g_xh + (size_t)tokA * HDIM + ak;
  const int bkr = tid >> 3, bc = (tid & 7) * 8;
  const size_t woff = (size_t)e * HDIM * IDIM + (size_t)bkr * IDIM + n0 + bc;
  const __half* pb1 = w1 + woff;
  const __half* pb3 = w3 + woff;

  const uint32_t sb = (uint32_t)__cvta_generic_to_shared(sm);
  const uint32_t dA = sb + (uint32_t)(ar * 40 + ak) * 2;
  const uint32_t dB1 = sb + (uint32_t)(5120 + bkr * 72 + bc) * 2;
  const uint32_t dB3 = dB1 + 2304 * 2;

#define G1FILL(kt, s)                                                         \
  do {                                                                        \
    uint32_t so = (uint32_t)(s)*G1_SST;                                       \
    const __half* a1 = pxh + (size_t)(kt) * 32;                               \
    CP16(dA + so, a1);                                                        \
    CP16(dA + so + 16, a1 + 8);                                               \
    const __half* b1 = pb1 + (size_t)(kt) * 32 * IDIM;                        \
    const __half* b3 = pb3 + (size_t)(kt) * 32 * IDIM;                        \
    CP16(dB1 + so, b1);                                                       \
    CP16(dB3 + so, b3);                                                       \
  } while (0)

  const int a_r = wm * 32 + (lane & 15);
  const int a_k = (lane >> 4) * 8;
  const uint32_t aA = sb + (uint32_t)(a_r * 40 + a_k) * 2;
  const int b_r = lane & 15;
  const int b_c = wn * 32 + (lane >> 4) * 8;
  const uint32_t aB = sb + (uint32_t)(5120 + b_r * 72 + b_c) * 2;

  float accg[2][4][4] = {}, accu[2][4][4] = {};
  const int KT = HDIM / 32;  // 64

  G1FILL(0, 0); CPCOMMIT();
  G1FILL(1, 1); CPCOMMIT();
  G1FILL(2, 2); CPCOMMIT();

  int s = 0;
  for (int kt = 0; kt < KT; kt++) {
    CPWAIT2();
    __syncthreads();
    if (kt + 3 < KT) {
      G1FILL(kt + 3, (s + 3) & 3);
    }
    CPCOMMIT();
    const uint32_t so = (uint32_t)s * G1_SST;
#pragma unroll
    for (int ks = 0; ks < 2; ks++) {
      uint32_t af[2][4];
#pragma unroll
      for (int mt = 0; mt < 2; mt++) {
        uint32_t addr = aA + so + (uint32_t)(mt * 16 * 40 + ks * 16) * 2;
        LDSM4(af[mt], addr);
      }
      uint32_t b1f[2][4], b3f[2][4];
#pragma unroll
      for (int h = 0; h < 2; h++) {
        uint32_t addr = aB + so + (uint32_t)(ks * 16 * 72 + h * 16) * 2;
        LDSM4T(b1f[h], addr);
        LDSM4T(b3f[h], addr + 2304 * 2);
      }
#pragma unroll
      for (int mt = 0; mt < 2; mt++) {
#pragma unroll
        for (int nt = 0; nt < 4; nt++) {
          const uint32_t* q1 = &b1f[nt >> 1][(nt & 1) * 2];
          const uint32_t* q3 = &b3f[nt >> 1][(nt & 1) * 2];
          MMAF16(accg[mt][nt], af[mt], q1);
          MMAF16(accu[mt][nt], af[mt], q3);
        }
      }
    }
    s = (s + 1) & 3;
  }

  // epilogue: w * silu(g)*u -> g_hh (fp16), gate weight folded here
#pragma unroll
  for (int mt = 0; mt < 2; mt++) {
    int rb = wm * 32 + mt * 16 + (lane >> 2);
#pragma unroll
    for (int hlf = 0; hlf < 2; hlf++) {
      int r = rb + hlf * 8;
      if (m0 + r >= cnt) continue;
      float wgt = g_rows_w[base + m0 + r];
      size_t rowb = (base + m0 + r) * IDIM + n0 + wn * 32;
#pragma unroll
      for (int nt = 0; nt < 4; nt++) {
        float gg0 = accg[mt][nt][hlf * 2 + 0], gg1 = accg[mt][nt][hlf * 2 + 1];
        float uu0 = accu[mt][nt][hlf * 2 + 0], uu1 = accu[mt][nt][hlf * 2 + 1];
        float h0 = gg0 / (1.f + __expf(-gg0)) * uu0 * wgt;
        float h1 = gg1 / (1.f + __expf(-gg1)) * uu1 * wgt;
        int col = nt * 8 + (lane & 3) * 2;
        *(__half2*)&g_hh[rowb + col] = __floats2half2_rn(h0, h1);
      }
    }
  }
}

// ============================================================
// GEMM2: out[t] += (h @ w2_e)   (weight pre-folded into h)
// half=0: tiles [0, g_nt_half); half=1: tiles [g_nt_half, g_ntiles)
// BM=128, BN=128, BK=32, 256 thr, warps 4Mx2N, warp tile 32x64
// smem/stage (halves): A 5120 | B 32*136=4352 = 9472
// 4 stages, 2 CTAs/SM
// ============================================================
constexpr uint32_t G2_SST = 9472u * 2;

__global__ __launch_bounds__(256, 2) void gemm2_kernel(
    const __half* __restrict__ w2, float* __restrict__ out, int half) {
  extern __shared__ __half sm[];
  const int tile = (half ? g_nt_half : 0) + blockIdx.x;
  const int tile_end = half ? g_ntiles : g_nt_half;
  if (tile >= tile_end) return;
  const int e = g_tile_e[tile];
  const int m0 = g_tile_m[tile];
  const size_t base = (size_t)e * CAP;
  const int cnt = g_counts[e];
  const int n0 = blockIdx.y * 128;

  const int tid = threadIdx.x, lane = tid & 31, warp = tid >> 5;
  const int wm = warp >> 1, wn = warp & 1;

  const int ar = tid >> 1, ak = (tid & 1) * 16;
  const int arow = m0 + ar;
  const size_t aidx = base + (arow < cnt ? arow : cnt - 1);
  const __half* pah = g_hh + aidx * IDIM + ak;
  const int bkr = tid >> 3, bc = (tid & 7) * 8;
  const __half* pb = w2 + (size_t)e * IDIM * HDIM + (size_t)bkr * HDIM + n0 + bc;

  const uint32_t sb = (uint32_t)__cvta_generic_to_shared(sm);
  const uint32_t dA = sb + (uint32_t)(ar * 40 + ak) * 2;
  const uint32_t dB = sb + (uint32_t)(5120 + bkr * 136 + bc) * 2;

#define G2FILL(kt, s)                                                         \
  do {                                                                        \
    uint32_t so = (uint32_t)(s)*G2_SST;                                       \
    const __half* a1 = pah + (size_t)(kt) * 32;                               \
    CP16(dA + so, a1);                                                        \
    CP16(dA + so + 16, a1 + 8);                                               \
    const __half* b = pb + (size_t)(kt) * 32 * HDIM;                          \
    CP16(dB + so, b);                                                         \
    CP16(dB + so + 128, b + 64);                                              \
  } while (0)

  const int a_r = wm * 32 + (lane & 15);
  const int a_k = (lane >> 4) * 8;
  const uint32_t aA = sb + (uint32_t)(a_r * 40 + a_k) * 2;
  const int b_r = lane & 15;
  const int b_c0 = wn * 64 + (lane >> 4) * 8;
  const uint32_t aB = sb + (uint32_t)(5120 + b_r * 136 + b_c0) * 2;

  float acc[2][8][4] = {};
  const int KT = IDIM / 32;  // 44

  G2FILL(0, 0); CPCOMMIT();
  G2FILL(1, 1); CPCOMMIT();
  G2FILL(2, 2); CPCOMMIT();

  int s = 0;
  for (int kt = 0; kt < KT; kt++) {
    CPWAIT2();
    __syncthreads();
    if (kt + 3 < KT) {
      G2FILL(kt + 3, (s + 3) & 3);
    }
    CPCOMMIT();
    const uint32_t so = (uint32_t)s * G2_SST;
#pragma unroll
    for (int ks = 0; ks < 2; ks++) {
      uint32_t af[2][4];
#pragma unroll
      for (int mt = 0; mt < 2; mt++) {
        uint32_t addr = aA + so + (uint32_t)(mt * 16 * 40 + ks * 16) * 2;
        LDSM4(af[mt], addr);
      }
      uint32_t bf[4][4];
#pragma unroll
      for (int h = 0; h < 4; h++) {
        uint32_t addr = aB + so + (uint32_t)(ks * 16 * 136 + h * 16) * 2;
        LDSM4T(bf[h], addr);
      }
#pragma unroll
      for (int mt = 0; mt < 2; mt++) {
#pragma unroll
        for (int nt = 0; nt < 8; nt++) {
          const uint32_t* q = &bf[nt >> 1][(nt & 1) * 2];
          MMAF16(acc[mt][nt], af[mt], q);
        }
      }
    }
    s = (s + 1) & 3;
  }

  // epilogue: atomic scatter-add (weights pre-folded)
#pragma unroll
  for (int mt = 0; mt < 2; mt++) {
    int rb = wm * 32 + mt * 16 + (lane >> 2);
#pragma unroll
    for (int hlf = 0; hlf < 2; hlf++) {
      int r = rb + hlf * 8;
      int gr = m0 + r;
      if (gr >= cnt) continue;
      int tok = g_rows_t[base + gr];
      float* orow = out + (size_t)tok * HDIM + n0 + wn * 64;
#pragma unroll
      for (int nt = 0; nt < 8; nt++) {
        int col = nt * 8 + (lane & 3) * 2;
        atomicAdd(&orow[col], acc[mt][nt][hlf * 2 + 0]);
        atomicAdd(&orow[col + 1], acc[mt][nt][hlf * 2 + 1]);
      }
    }
  }
}

// ---------------- launch ----------------
extern "C" void kernel_launch(void* const* d_in, const int* in_sizes, int n_in,
                              void* d_out, int out_size) {
  const float* x  = (const float*)d_in[0];
  const float* gw = (const float*)d_in[1];
  const float* w1 = (const float*)d_in[2];
  const float* w3 = (const float*)d_in[3];
  const float* w2 = (const float*)d_in[4];
  float* out = (float*)d_out;

  const int T = in_sizes[0] / HDIM;  // 8192
  const int R = 2 * T;

  static bool inited = false;
  static cudaStream_t s2, s3;
  static cudaEvent_t evRoot, evW13A, evW13B, evW2, evMs, ev1A, ev2A;
  static int* cnt_addr = nullptr;
  if (!inited) {
    cudaStreamCreateWithFlags(&s2, cudaStreamNonBlocking);
    cudaStreamCreateWithFlags(&s3, cudaStreamNonBlocking);
    cudaEventCreateWithFlags(&evRoot, cudaEventDisableTiming);
    cudaEventCreateWithFlags(&evW13A, cudaEventDisableTiming);
    cudaEventCreateWithFlags(&evW13B, cudaEventDisableTiming);
    cudaEventCreateWithFlags(&evW2, cudaEventDisableTiming);
    cudaEventCreateWithFlags(&evMs, cudaEventDisableTiming);
    cudaEventCreateWithFlags(&ev1A, cudaEventDisableTiming);
    cudaEventCreateWithFlags(&ev2A, cudaEventDisableTiming);
    cudaGetSymbolAddress((void**)&cnt_addr, g_counts);
    cudaFuncSetAttribute(gemm1_kernel,
                         cudaFuncAttributeMaxDynamicSharedMemorySize,
                         (int)(G1_SST * 4));
    cudaFuncSetAttribute(gemm2_kernel,
                         cudaFuncAttributeMaxDynamicSharedMemorySize,
                         (int)(G2_SST * 4));
    inited = true;
  }

  __half *w1h, *w3h, *w2h;
  cudaGetSymbolAddress((void**)&w1h, g_w1h);
  cudaGetSymbolAddress((void**)&w3h, g_w3h);
  cudaGetSymbolAddress((void**)&w2h, g_w2h);

  // fork side streams off the main (capture-origin) stream
  cudaEventRecord(evRoot, 0);
  cudaStreamWaitEvent(s2, evRoot, 0);
  cudaStreamWaitEvent(s3, evRoot, 0);

  // s3: zero the output (only gemm2 depends on it)
  cudaMemsetAsync(out, 0, (size_t)out_size * sizeof(float), s3);
  cudaEventRecord(evMs, s3);

  // s2: w1/w3 conversion in expert halves, then w2
  convw13_kernel<<<(2 * NW4H + 255) / 256, 256, 0, s2>>>(w1, w3, 0);
  cudaEventRecord(evW13A, s2);
  convw13_kernel<<<(2 * NW4H + 255) / 256, 256, 0, s2>>>(w1, w3, 1);
  cudaEventRecord(evW13B, s2);
  convw2_kernel<<<(NW4 + 255) / 256, 256, 0, s2>>>(w2);
  cudaEventRecord(evW2, s2);

  // main: routing (overlaps with conversions)
  cudaMemsetAsync(cnt_addr, 0, NEXP * sizeof(int), 0);
  router_kernel<<<(T / 4 + 3) / 4, 128>>>(x, gw, T);   // 512 blocks of 128
  scatter_kernel<<<(R + 255) / 256, 256>>>(R);
  tilemap_kernel<<<1, 1>>>();

  // main: gemm1 half A (experts 0-7; needs conv half A + routing)
  cudaStreamWaitEvent(0, evW13A, 0);
  dim3 g1(HALF_MAX, IDIM / 64, 1);
  gemm1_kernel<<<g1, 256, G1_SST * 4>>>(w1h, w3h, 0);
  cudaEventRecord(ev1A, 0);

  // main: gemm1 half B (needs conv half B)
  cudaStreamWaitEvent(0, evW13B, 0);
  gemm1_kernel<<<g1, 256, G1_SST * 4>>>(w1h, w3h, 1);

  // s3: gemm2 half A (starts as soon as gemm1A + w2 conv + memset done)
  cudaStreamWaitEvent(s3, ev1A, 0);
  cudaStreamWaitEvent(s3, evW2, 0);
  dim3 g2(HALF_MAX, HDIM / 128, 1);
  gemm2_kernel<<<g2, 256, G2_SST * 4, s3>>>(w2h, out, 0);
  cudaEventRecord(ev2A, s3);

  // main: gemm2 half B (after gemm1B in-stream; needs w2 + memset)
  cudaStreamWaitEvent(0, evW2, 0);
  cudaStreamWaitEvent(0, evMs, 0);
  gemm2_kernel<<<g2, 256, G2_SST * 4>>>(w2h, out, 1);

  // join forked branch back into the origin stream before capture ends
  cudaStreamWaitEvent(0, ev2A, 0);
  join_kernel<<<1, 1>>>();
}

// round 17
// speedup vs baseline: 1.0197x; 1.0197x over previous
#include <cuda_runtime.h>
#include <cuda_fp16.h>
#include <cstdint>

// ---------------- problem constants ----------------
constexpr int HDIM = 2048;
constexpr int IDIM = 1408;
constexpr int NEXP = 16;
constexpr int TMAX = 8192;
constexpr int RMAX = 2 * TMAX;
constexpr int CAP  = RMAX;                    // per-expert row capacity
constexpr int TILE_MAX = RMAX / 128 + NEXP;   // 144 (all experts)
constexpr int HALF_MAX = RMAX / 128 + 8;      // 136 (one expert half, worst case)

// ---------------- device scratch (static, no runtime allocs) ----------------
__device__ int   g_counts[NEXP];
__device__ int   g_rows_t[(size_t)NEXP * CAP];
__device__ float g_rows_w[(size_t)NEXP * CAP];
__device__ int   g_tile_e[TILE_MAX];
__device__ int   g_tile_m[TILE_MAX];
__device__ int   g_ntiles;
__device__ int   g_nt_half;   // tiles belonging to experts 0..7

__device__ alignas(16) __half g_w1h[(size_t)NEXP * HDIM * IDIM];  // [e][K=H][N=I]
__device__ alignas(16) __half g_w3h[(size_t)NEXP * HDIM * IDIM];
__device__ alignas(16) __half g_w2h[(size_t)NEXP * IDIM * HDIM];  // [e][K=I][N=H]
__device__ alignas(16) __half g_xh[(size_t)TMAX * HDIM];
__device__ alignas(16) __half g_hh[(size_t)NEXP * CAP * IDIM];

// ---------------- asm helpers ----------------
#define LDSM4(R, addr)                                                        \
  asm volatile("ldmatrix.sync.aligned.m8n8.x4.shared.b16 {%0,%1,%2,%3},[%4];" \
               : "=r"((R)[0]), "=r"((R)[1]), "=r"((R)[2]), "=r"((R)[3])       \
               : "r"(addr))

#define LDSM4T(R, addr)                                                             \
  asm volatile("ldmatrix.sync.aligned.m8n8.x4.trans.shared.b16 {%0,%1,%2,%3},[%4];" \
               : "=r"((R)[0]), "=r"((R)[1]), "=r"((R)[2]), "=r"((R)[3])             \
               : "r"(addr))

#define MMAF16(D, A, B)                                                       \
  asm volatile("mma.sync.aligned.m16n8k16.row.col.f32.f16.f16.f32 "           \
               "{%0,%1,%2,%3},{%4,%5,%6,%7},{%8,%9},{%0,%1,%2,%3};"           \
               : "+f"((D)[0]), "+f"((D)[1]), "+f"((D)[2]), "+f"((D)[3])       \
               : "r"((A)[0]), "r"((A)[1]), "r"((A)[2]), "r"((A)[3]),          \
                 "r"((B)[0]), "r"((B)[1]))

#define CP16(dst, src)                                                        \
  asm volatile("cp.async.cg.shared.global [%0],[%1],16;" ::"r"(dst), "l"(src))
#define CPCOMMIT() asm volatile("cp.async.commit_group;")
#define CPWAIT2() asm volatile("cp.async.wait_group 2;")

// ---------------- conversion pre-passes (side stream) ----------------
constexpr int NW4 = NEXP * HDIM * IDIM / 4;  // 11,534,336
constexpr int NW4H = NW4 / 2;                // 8 experts worth of float4

// convert expert-half `half` of w1 and w3
__global__ void convw13_kernel(const float* __restrict__ w1,
                               const float* __restrict__ w3, int half) {
  int i = blockIdx.x * blockDim.x + threadIdx.x;
  const float* src;
  __half* dst;
  int li;
  if (i < NW4H) {
    src = w1; dst = g_w1h; li = half * NW4H + i;
  } else {
    li = i - NW4H;
    if (li >= NW4H) return;
    src = w3; dst = g_w3h; li = half * NW4H + li;
  }
  float4 f = __ldcs(((const float4*)src) + li);
  __half2 a = __floats2half2_rn(f.x, f.y);
  __half2 b = __floats2half2_rn(f.z, f.w);
  uint2 u;
  u.x = *(const uint32_t*)&a;
  u.y = *(const uint32_t*)&b;
  ((uint2*)dst)[li] = u;
}

__global__ void convw2_kernel(const float* __restrict__ w2) {
  int i = blockIdx.x * blockDim.x + threadIdx.x;
  if (i >= NW4) return;
  float4 f = __ldcs(((const float4*)w2) + i);
  __half2 a = __floats2half2_rn(f.x, f.y);
  __half2 b = __floats2half2_rn(f.z, f.w);
  uint2 u;
  u.x = *(const uint32_t*)&a;
  u.y = *(const uint32_t*)&b;
  ((uint2*)g_w2h)[i] = u;
}

__global__ void join_kernel() {}

// ---------------- router: 2 tokens per warp; emits g_xh + direct scatter ----
__global__ void router_kernel(const float* __restrict__ x,
                              const float* __restrict__ gw, int T) {
  const int gwarp = (blockIdx.x * blockDim.x + threadIdx.x) >> 5;
  const int lane = threadIdx.x & 31;
  const int t0 = gwarp * 2;
  if (t0 >= T) return;

  const float* xr0 = x + (size_t)t0 * HDIM;
  __half* xh0 = g_xh + (size_t)t0 * HDIM;
  float acc[2][NEXP];
#pragma unroll
  for (int i = 0; i < 2; i++)
#pragma unroll
    for (int j = 0; j < NEXP; j++) acc[i][j] = 0.f;

  for (int k = lane; k < HDIM; k += 32) {
    const float4* g4 = (const float4*)(gw + (size_t)k * NEXP);
    float4 g0 = g4[0], g1 = g4[1], g2 = g4[2], g3 = g4[3];
    float xv0 = xr0[k];
    float xv1 = xr0[HDIM + k];
    xh0[k] = __float2half_rn(xv0);
    xh0[HDIM + k] = __float2half_rn(xv1);
#define RSTEP(i, xv)                                                          \
    acc[i][0] += (xv)*g0.x;  acc[i][1] += (xv)*g0.y;                          \
    acc[i][2] += (xv)*g0.z;  acc[i][3] += (xv)*g0.w;                          \
    acc[i][4] += (xv)*g1.x;  acc[i][5] += (xv)*g1.y;                          \
    acc[i][6] += (xv)*g1.z;  acc[i][7] += (xv)*g1.w;                          \
    acc[i][8] += (xv)*g2.x;  acc[i][9] += (xv)*g2.y;                          \
    acc[i][10] += (xv)*g2.z; acc[i][11] += (xv)*g2.w;                         \
    acc[i][12] += (xv)*g3.x; acc[i][13] += (xv)*g3.y;                         \
    acc[i][14] += (xv)*g3.z; acc[i][15] += (xv)*g3.w;
    RSTEP(0, xv0) RSTEP(1, xv1)
#undef RSTEP
  }
#pragma unroll
  for (int i = 0; i < 2; i++)
#pragma unroll
    for (int j = 0; j < NEXP; j++) {
#pragma unroll
      for (int o = 16; o > 0; o >>= 1)
        acc[i][j] += __shfl_xor_sync(0xffffffffu, acc[i][j], o);
    }

  if (lane < 2) {
    float v[NEXP];
#pragma unroll
    for (int j = 0; j < NEXP; j++) {
      float t = acc[0][j];
      if (lane == 1) t = acc[1][j];
      v[j] = t;
    }
    float b = -3.4e38f, s = -3.4e38f;
    int bi = 0, si = 0;
#pragma unroll
    for (int j = 0; j < NEXP; j++) {
      float w = v[j];
      if (w > b) { s = b; si = bi; b = w; bi = j; }
      else if (w > s) { s = w; si = j; }
    }
    float w0 = 1.f / (1.f + expf(s - b));
    int t = t0 + lane;
    // direct per-expert scatter (order within expert is value-irrelevant)
    int p = atomicAdd(&g_counts[bi], 1);
    g_rows_t[(size_t)bi * CAP + p] = t;
    g_rows_w[(size_t)bi * CAP + p] = w0;
    p = atomicAdd(&g_counts[si], 1);
    g_rows_t[(size_t)si * CAP + p] = t;
    g_rows_w[(size_t)si * CAP + p] = 1.f - w0;
  }
}

// ---------------- tile map (single thread; counts final after router) -------
__global__ void tilemap_kernel() {
  int nt = 0;
  for (int e = 0; e < NEXP; e++) {
    if (e == 8) g_nt_half = nt;
    int c = g_counts[e];
    for (int m = 0; m < c; m += 128) {
      g_tile_e[nt] = e;
      g_tile_m[nt] = m;
      nt++;
    }
  }
  g_ntiles = nt;
}

// ============================================================
// GEMM1: h = w * silu(Xe@w1) * (Xe@w3)   (single-pass fp16, weight folded)
// half=0: tiles [0, g_nt_half); half=1: tiles [g_nt_half, g_ntiles)
// BM=128, BN=64/matrix, BK=32, 256 thr, warps 4Mx2N, warp tile 32x32/matrix
// smem/stage (halves): A 128*40=5120 | B1 32*72=2304 | B3 2304 = 9728
// 4 stages, 2 CTAs/SM
// ============================================================
constexpr uint32_t G1_SST = 9728u * 2;

__global__ __launch_bounds__(256, 2) void gemm1_kernel(
    const __half* __restrict__ w1, const __half* __restrict__ w3, int half) {
  extern __shared__ __half sm[];
  const int tile = (half ? g_nt_half : 0) + blockIdx.x;
  const int tile_end = half ? g_ntiles : g_nt_half;
  if (tile >= tile_end) return;
  const int e = g_tile_e[tile];
  const int m0 = g_tile_m[tile];
  const size_t base = (size_t)e * CAP;
  const int cnt = g_counts[e];
  const int n0 = blockIdx.y * 64;

  const int tid = threadIdx.x, lane = tid & 31, warp = tid >> 5;
  const int wm = warp >> 1, wn = warp & 1;

  const int ar = tid >> 1, ak = (tid & 1) * 16;
  const int arow = m0 + ar;
  const int tokA = g_rows_t[base + (arow < cnt ? arow : cnt - 1)];
  const __half* pxh = g_xh + (size_t)tokA * HDIM + ak;
  const int bkr = tid >> 3, bc = (tid & 7) * 8;
  const size_t woff = (size_t)e * HDIM * IDIM + (size_t)bkr * IDIM + n0 + bc;
  const __half* pb1 = w1 + woff;
  const __half* pb3 = w3 + woff;

  const uint32_t sb = (uint32_t)__cvta_generic_to_shared(sm);
  const uint32_t dA = sb + (uint32_t)(ar * 40 + ak) * 2;
  const uint32_t dB1 = sb + (uint32_t)(5120 + bkr * 72 + bc) * 2;
  const uint32_t dB3 = dB1 + 2304 * 2;

#define G1FILL(kt, s)                                                         \
  do {                                                                        \
    uint32_t so = (uint32_t)(s)*G1_SST;                                       \
    const __half* a1 = pxh + (size_t)(kt) * 32;                               \
    CP16(dA + so, a1);                                                        \
    CP16(dA + so + 16, a1 + 8);                                               \
    const __half* b1 = pb1 + (size_t)(kt) * 32 * IDIM;                        \
    const __half* b3 = pb3 + (size_t)(kt) * 32 * IDIM;                        \
    CP16(dB1 + so, b1);                                                       \
    CP16(dB3 + so, b3);                                                       \
  } while (0)

  const int a_r = wm * 32 + (lane & 15);
  const int a_k = (lane >> 4) * 8;
  const uint32_t aA = sb + (uint32_t)(a_r * 40 + a_k) * 2;
  const int b_r = lane & 15;
  const int b_c = wn * 32 + (lane >> 4) * 8;
  const uint32_t aB = sb + (uint32_t)(5120 + b_r * 72 + b_c) * 2;

  float accg[2][4][4] = {}, accu[2][4][4] = {};
  const int KT = HDIM / 32;  // 64

  G1FILL(0, 0); CPCOMMIT();
  G1FILL(1, 1); CPCOMMIT();
  G1FILL(2, 2); CPCOMMIT();

  int s = 0;
  for (int kt = 0; kt < KT; kt++) {
    CPWAIT2();
    __syncthreads();
    if (kt + 3 < KT) {
      G1FILL(kt + 3, (s + 3) & 3);
    }
    CPCOMMIT();
    const uint32_t so = (uint32_t)s * G1_SST;
#pragma unroll
    for (int ks = 0; ks < 2; ks++) {
      uint32_t af[2][4];
#pragma unroll
      for (int mt = 0; mt < 2; mt++) {
        uint32_t addr = aA + so + (uint32_t)(mt * 16 * 40 + ks * 16) * 2;
        LDSM4(af[mt], addr);
      }
      uint32_t b1f[2][4], b3f[2][4];
#pragma unroll
      for (int h = 0; h < 2; h++) {
        uint32_t addr = aB + so + (uint32_t)(ks * 16 * 72 + h * 16) * 2;
        LDSM4T(b1f[h], addr);
        LDSM4T(b3f[h], addr + 2304 * 2);
      }
#pragma unroll
      for (int mt = 0; mt < 2; mt++) {
#pragma unroll
        for (int nt = 0; nt < 4; nt++) {
          const uint32_t* q1 = &b1f[nt >> 1][(nt & 1) * 2];
          const uint32_t* q3 = &b3f[nt >> 1][(nt & 1) * 2];
          MMAF16(accg[mt][nt], af[mt], q1);
          MMAF16(accu[mt][nt], af[mt], q3);
        }
      }
    }
    s = (s + 1) & 3;
  }

  // epilogue: w * silu(g)*u -> g_hh (fp16), gate weight folded here
#pragma unroll
  for (int mt = 0; mt < 2; mt++) {
    int rb = wm * 32 + mt * 16 + (lane >> 2);
#pragma unroll
    for (int hlf = 0; hlf < 2; hlf++) {
      int r = rb + hlf * 8;
      if (m0 + r >= cnt) continue;
      float wgt = g_rows_w[base + m0 + r];
      size_t rowb = (base + m0 + r) * IDIM + n0 + wn * 32;
#pragma unroll
      for (int nt = 0; nt < 4; nt++) {
        float gg0 = accg[mt][nt][hlf * 2 + 0], gg1 = accg[mt][nt][hlf * 2 + 1];
        float uu0 = accu[mt][nt][hlf * 2 + 0], uu1 = accu[mt][nt][hlf * 2 + 1];
        float h0 = gg0 / (1.f + __expf(-gg0)) * uu0 * wgt;
        float h1 = gg1 / (1.f + __expf(-gg1)) * uu1 * wgt;
        int col = nt * 8 + (lane & 3) * 2;
        *(__half2*)&g_hh[rowb + col] = __floats2half2_rn(h0, h1);
      }
    }
  }
}

// ============================================================
// GEMM2: out[t] += (h @ w2_e)   (weight pre-folded into h)
// half=0: tiles [0, g_nt_half); half=1: tiles [g_nt_half, g_ntiles)
// BM=128, BN=128, BK=32, 256 thr, warps 4Mx2N, warp tile 32x64
// smem/stage (halves): A 5120 | B 32*136=4352 = 9472
// 4 stages, 2 CTAs/SM
// ============================================================
constexpr uint32_t G2_SST = 9472u * 2;

__global__ __launch_bounds__(256, 2) void gemm2_kernel(
    const __half* __restrict__ w2, float* __restrict__ out, int half) {
  extern __shared__ __half sm[];
  const int tile = (half ? g_nt_half : 0) + blockIdx.x;
  const int tile_end = half ? g_ntiles : g_nt_half;
  if (tile >= tile_end) return;
  const int e = g_tile_e[tile];
  const int m0 = g_tile_m[tile];
  const size_t base = (size_t)e * CAP;
  const int cnt = g_counts[e];
  const int n0 = blockIdx.y * 128;

  const int tid = threadIdx.x, lane = tid & 31, warp = tid >> 5;
  const int wm = warp >> 1, wn = warp & 1;

  const int ar = tid >> 1, ak = (tid & 1) * 16;
  const int arow = m0 + ar;
  const size_t aidx = base + (arow < cnt ? arow : cnt - 1);
  const __half* pah = g_hh + aidx * IDIM + ak;
  const int bkr = tid >> 3, bc = (tid & 7) * 8;
  const __half* pb = w2 + (size_t)e * IDIM * HDIM + (size_t)bkr * HDIM + n0 + bc;

  const uint32_t sb = (uint32_t)__cvta_generic_to_shared(sm);
  const uint32_t dA = sb + (uint32_t)(ar * 40 + ak) * 2;
  const uint32_t dB = sb + (uint32_t)(5120 + bkr * 136 + bc) * 2;

#define G2FILL(kt, s)                                                         \
  do {                                                                        \
    uint32_t so = (uint32_t)(s)*G2_SST;                                       \
    const __half* a1 = pah + (size_t)(kt) * 32;                               \
    CP16(dA + so, a1);                                                        \
    CP16(dA + so + 16, a1 + 8);                                               \
    const __half* b = pb + (size_t)(kt) * 32 * HDIM;                          \
    CP16(dB + so, b);                                                         \
    CP16(dB + so + 128, b + 64);                                              \
  } while (0)

  const int a_r = wm * 32 + (lane & 15);
  const int a_k = (lane >> 4) * 8;
  const uint32_t aA = sb + (uint32_t)(a_r * 40 + a_k) * 2;
  const int b_r = lane & 15;
  const int b_c0 = wn * 64 + (lane >> 4) * 8;
  const uint32_t aB = sb + (uint32_t)(5120 + b_r * 136 + b_c0) * 2;

  float acc[2][8][4] = {};
  const int KT = IDIM / 32;  // 44

  G2FILL(0, 0); CPCOMMIT();
  G2FILL(1, 1); CPCOMMIT();
  G2FILL(2, 2); CPCOMMIT();

  int s = 0;
  for (int kt = 0; kt < KT; kt++) {
    CPWAIT2();
    __syncthreads();
    if (kt + 3 < KT) {
      G2FILL(kt + 3, (s + 3) & 3);
    }
    CPCOMMIT();
    const uint32_t so = (uint32_t)s * G2_SST;
#pragma unroll
    for (int ks = 0; ks < 2; ks++) {
      uint32_t af[2][4];
#pragma unroll
      for (int mt = 0; mt < 2; mt++) {
        uint32_t addr = aA + so + (uint32_t)(mt * 16 * 40 + ks * 16) * 2;
        LDSM4(af[mt], addr);
      }
      uint32_t bf[4][4];
#pragma unroll
      for (int h = 0; h < 4; h++) {
        uint32_t addr = aB + so + (uint32_t)(ks * 16 * 136 + h * 16) * 2;
        LDSM4T(bf[h], addr);
      }
#pragma unroll
      for (int mt = 0; mt < 2; mt++) {
#pragma unroll
        for (int nt = 0; nt < 8; nt++) {
          const uint32_t* q = &bf[nt >> 1][(nt & 1) * 2];
          MMAF16(acc[mt][nt], af[mt], q);
        }
      }
    }
    s = (s + 1) & 3;
  }

  // epilogue: atomic scatter-add (weights pre-folded)
#pragma unroll
  for (int mt = 0; mt < 2; mt++) {
    int rb = wm * 32 + mt * 16 + (lane >> 2);
#pragma unroll
    for (int hlf = 0; hlf < 2; hlf++) {
      int r = rb + hlf * 8;
      int gr = m0 + r;
      if (gr >= cnt) continue;
      int tok = g_rows_t[base + gr];
      float* orow = out + (size_t)tok * HDIM + n0 + wn * 64;
#pragma unroll
      for (int nt = 0; nt < 8; nt++) {
        int col = nt * 8 + (lane & 3) * 2;
        atomicAdd(&orow[col], acc[mt][nt][hlf * 2 + 0]);
        atomicAdd(&orow[col + 1], acc[mt][nt][hlf * 2 + 1]);
      }
    }
  }
}

// ---------------- launch ----------------
extern "C" void kernel_launch(void* const* d_in, const int* in_sizes, int n_in,
                              void* d_out, int out_size) {
  const float* x  = (const float*)d_in[0];
  const float* gw = (const float*)d_in[1];
  const float* w1 = (const float*)d_in[2];
  const float* w3 = (const float*)d_in[3];
  const float* w2 = (const float*)d_in[4];
  float* out = (float*)d_out;

  const int T = in_sizes[0] / HDIM;  // 8192

  static bool inited = false;
  static cudaStream_t s2, s3;
  static cudaEvent_t evRoot, evW13A, evW13B, evW2, evMs, ev1A, ev2A;
  static int* cnt_addr = nullptr;
  if (!inited) {
    cudaStreamCreateWithFlags(&s2, cudaStreamNonBlocking);
    cudaStreamCreateWithFlags(&s3, cudaStreamNonBlocking);
    cudaEventCreateWithFlags(&evRoot, cudaEventDisableTiming);
    cudaEventCreateWithFlags(&evW13A, cudaEventDisableTiming);
    cudaEventCreateWithFlags(&evW13B, cudaEventDisableTiming);
    cudaEventCreateWithFlags(&evW2, cudaEventDisableTiming);
    cudaEventCreateWithFlags(&evMs, cudaEventDisableTiming);
    cudaEventCreateWithFlags(&ev1A, cudaEventDisableTiming);
    cudaEventCreateWithFlags(&ev2A, cudaEventDisableTiming);
    cudaGetSymbolAddress((void**)&cnt_addr, g_counts);
    cudaFuncSetAttribute(gemm1_kernel,
                         cudaFuncAttributeMaxDynamicSharedMemorySize,
                         (int)(G1_SST * 4));
    cudaFuncSetAttribute(gemm2_kernel,
                         cudaFuncAttributeMaxDynamicSharedMemorySize,
                         (int)(G2_SST * 4));
    inited = true;
  }

  __half *w1h, *w3h, *w2h;
  cudaGetSymbolAddress((void**)&w1h, g_w1h);
  cudaGetSymbolAddress((void**)&w3h, g_w3h);
  cudaGetSymbolAddress((void**)&w2h, g_w2h);

  // fork side streams off the main (capture-origin) stream
  cudaEventRecord(evRoot, 0);
  cudaStreamWaitEvent(s2, evRoot, 0);
  cudaStreamWaitEvent(s3, evRoot, 0);

  // s3: zero the output (only gemm2 depends on it)
  cudaMemsetAsync(out, 0, (size_t)out_size * sizeof(float), s3);
  cudaEventRecord(evMs, s3);

  // s2: w1/w3 conversion in expert halves, then w2
  convw13_kernel<<<(2 * NW4H + 255) / 256, 256, 0, s2>>>(w1, w3, 0);
  cudaEventRecord(evW13A, s2);
  convw13_kernel<<<(2 * NW4H + 255) / 256, 256, 0, s2>>>(w1, w3, 1);
  cudaEventRecord(evW13B, s2);
  convw2_kernel<<<(NW4 + 255) / 256, 256, 0, s2>>>(w2);
  cudaEventRecord(evW2, s2);

  // main: routing (router does x-convert + top2 + direct scatter)
  cudaMemsetAsync(cnt_addr, 0, NEXP * sizeof(int), 0);
  router_kernel<<<T / 8, 128>>>(x, gw, T);   // 1024 blocks, 2 tok/warp
  tilemap_kernel<<<1, 1>>>();

  // main: gemm1 half A (experts 0-7; needs conv half A + routing)
  cudaStreamWaitEvent(0, evW13A, 0);
  dim3 g1(HALF_MAX, IDIM / 64, 1);
  gemm1_kernel<<<g1, 256, G1_SST * 4>>>(w1h, w3h, 0);
  cudaEventRecord(ev1A, 0);

  // main: gemm1 half B (needs conv half B)
  cudaStreamWaitEvent(0, evW13B, 0);
  gemm1_kernel<<<g1, 256, G1_SST * 4>>>(w1h, w3h, 1);

  // s3: gemm2 half A (starts as soon as gemm1A + w2 conv + memset done)
  cudaStreamWaitEvent(s3, ev1A, 0);
  cudaStreamWaitEvent(s3, evW2, 0);
  dim3 g2(HALF_MAX, HDIM / 128, 1);
  gemm2_kernel<<<g2, 256, G2_SST * 4, s3>>>(w2h, out, 0);
  cudaEventRecord(ev2A, s3);

  // main: gemm2 half B (after gemm1B in-stream; needs w2 + memset)
  cudaStreamWaitEvent(0, evW2, 0);
  cudaStreamWaitEvent(0, evMs, 0);
  gemm2_kernel<<<g2, 256, G2_SST * 4>>>(w2h, out, 1);

  // join forked branch back into the origin stream before capture ends
  cudaStreamWaitEvent(0, ev2A, 0);
  join_kernel<<<1, 1>>>();
}